// round 1
// baseline (speedup 1.0000x reference)
#include <cuda_runtime.h>
#include <math.h>

// Problem constants
#define BB 2
#define SS 2048
#define DM 1024
#define NH 16
#define DK 64
#define BH (BB*NH)          // 32
#define M_ROWS (BB*SS)      // 4096

// Scratch (allocation-free rule: __device__ globals)
__device__ float g_Q[BH * SS * DK];    // (b,h,s,d) head-major
__device__ float g_K[BH * SS * DK];
__device__ float g_V[BH * SS * DK];
__device__ float g_ctx[M_ROWS * DM];   // (b,s,d_model)

// ---------------------------------------------------------------------------
// Kernel 1/5: C = X(M x 1024) @ W(1024 x 1024) + bias
// head_major=1 -> write to (b,h,s,d) layout; else row-major (m,n)
// Block tile 64x64, BK=16, 256 threads, 4x4 per-thread micro-tile.
// ---------------------------------------------------------------------------
__global__ __launch_bounds__(256) void proj_kernel(
    const float* __restrict__ X, const float* __restrict__ W,
    const float* __restrict__ bias, float* __restrict__ out, int head_major)
{
    __shared__ float As[16][64];
    __shared__ float Bs[16][64];

    const int tid = threadIdx.x;
    const int tx = tid & 15;          // 0..15 -> col group
    const int ty = tid >> 4;          // 0..15 -> row group
    const int rowBase = blockIdx.y * 64;
    const int colBase = blockIdx.x * 64;

    // load mapping
    const int ar  = tid >> 2;             // 0..63 row of A tile
    const int ac4 = (tid & 3) * 4;        // k offset (float4)
    const int bkr = tid >> 4;             // 0..15 k row of B tile
    const int bc4 = (tid & 15) * 4;       // n offset (float4)

    float acc[4][4];
    #pragma unroll
    for (int i = 0; i < 4; i++)
        #pragma unroll
        for (int j = 0; j < 4; j++) acc[i][j] = 0.0f;

    for (int k0 = 0; k0 < 1024; k0 += 16) {
        float4 av = *reinterpret_cast<const float4*>(&X[(size_t)(rowBase + ar) * 1024 + k0 + ac4]);
        As[ac4 + 0][ar] = av.x; As[ac4 + 1][ar] = av.y;
        As[ac4 + 2][ar] = av.z; As[ac4 + 3][ar] = av.w;
        float4 bv = *reinterpret_cast<const float4*>(&W[(size_t)(k0 + bkr) * 1024 + colBase + bc4]);
        *reinterpret_cast<float4*>(&Bs[bkr][bc4]) = bv;
        __syncthreads();

        #pragma unroll
        for (int k = 0; k < 16; k++) {
            float4 a = *reinterpret_cast<const float4*>(&As[k][ty * 4]);
            float4 b = *reinterpret_cast<const float4*>(&Bs[k][tx * 4]);
            float ai[4] = {a.x, a.y, a.z, a.w};
            float bj[4] = {b.x, b.y, b.z, b.w};
            #pragma unroll
            for (int i = 0; i < 4; i++)
                #pragma unroll
                for (int j = 0; j < 4; j++)
                    acc[i][j] = fmaf(ai[i], bj[j], acc[i][j]);
        }
        __syncthreads();
    }

    #pragma unroll
    for (int i = 0; i < 4; i++) {
        const int m = rowBase + ty * 4 + i;
        #pragma unroll
        for (int j = 0; j < 4; j++) {
            const int n = colBase + tx * 4 + j;
            const float v = acc[i][j] + bias[n];
            if (head_major) {
                const int b = m >> 11;        // m / 2048
                const int s = m & 2047;
                const int h = n >> 6;         // n / 64
                const int d = n & 63;
                out[(((size_t)(b * NH + h) * SS + s) << 6) + d] = v;
            } else {
                out[(size_t)m * DM + n] = v;
            }
        }
    }
}

// ---------------------------------------------------------------------------
// Kernel 2: scores[bh][i][j] = (1/8) * dot(Q[bh][i], K[bh][j]);  K-dim = 64.
// Block tile 64x64, single K pass, 256 threads, 4x4 micro-tile.
// ---------------------------------------------------------------------------
__global__ __launch_bounds__(256) void scores_kernel(
    const float* __restrict__ Q, const float* __restrict__ K,
    float* __restrict__ attn)
{
    __shared__ float Qs[64][64];   // [d][i]
    __shared__ float Ks[64][64];   // [d][j]

    const int bh = blockIdx.z;
    const float* Qh = Q + (size_t)bh * SS * DK;
    const float* Kh = K + (size_t)bh * SS * DK;

    const int tid = threadIdx.x;
    const int tx = tid & 15;
    const int ty = tid >> 4;
    const int iBase = blockIdx.y * 64;
    const int jBase = blockIdx.x * 64;

    // each thread loads 16 floats per tile (4 x float4)
    #pragma unroll
    for (int c = 0; c < 4; c++) {
        const int lin = tid + c * 256;
        const int r  = lin >> 4;          // row within tile (0..63)
        const int d4 = (lin & 15) * 4;    // d offset
        float4 qv = *reinterpret_cast<const float4*>(&Qh[(size_t)(iBase + r) * DK + d4]);
        Qs[d4 + 0][r] = qv.x; Qs[d4 + 1][r] = qv.y;
        Qs[d4 + 2][r] = qv.z; Qs[d4 + 3][r] = qv.w;
        float4 kv = *reinterpret_cast<const float4*>(&Kh[(size_t)(jBase + r) * DK + d4]);
        Ks[d4 + 0][r] = kv.x; Ks[d4 + 1][r] = kv.y;
        Ks[d4 + 2][r] = kv.z; Ks[d4 + 3][r] = kv.w;
    }
    __syncthreads();

    float acc[4][4];
    #pragma unroll
    for (int i = 0; i < 4; i++)
        #pragma unroll
        for (int j = 0; j < 4; j++) acc[i][j] = 0.0f;

    #pragma unroll
    for (int k = 0; k < 64; k++) {
        float4 a = *reinterpret_cast<const float4*>(&Qs[k][ty * 4]);
        float4 b = *reinterpret_cast<const float4*>(&Ks[k][tx * 4]);
        float ai[4] = {a.x, a.y, a.z, a.w};
        float bj[4] = {b.x, b.y, b.z, b.w};
        #pragma unroll
        for (int i = 0; i < 4; i++)
            #pragma unroll
            for (int j = 0; j < 4; j++)
                acc[i][j] = fmaf(ai[i], bj[j], acc[i][j]);
    }

    const float scale = 0.125f;   // 1/sqrt(64)
    #pragma unroll
    for (int i = 0; i < 4; i++) {
        const int gi = iBase + ty * 4 + i;
        float* row = attn + ((size_t)bh * SS + gi) * SS;
        #pragma unroll
        for (int j = 0; j < 4; j++) {
            row[jBase + tx * 4 + j] = acc[i][j] * scale;
        }
    }
}

// ---------------------------------------------------------------------------
// Kernel 3: in-place row softmax over 2048 elements. One block per row.
// ---------------------------------------------------------------------------
__global__ __launch_bounds__(256) void softmax_kernel(float* __restrict__ attn)
{
    __shared__ float red[8];
    float* row = attn + (size_t)blockIdx.x * SS;
    const int tid = threadIdx.x;
    const int lane = tid & 31;
    const int warp = tid >> 5;

    float4 v0 = *reinterpret_cast<const float4*>(&row[tid * 8]);
    float4 v1 = *reinterpret_cast<const float4*>(&row[tid * 8 + 4]);
    float vals[8] = {v0.x, v0.y, v0.z, v0.w, v1.x, v1.y, v1.z, v1.w};

    // max reduce
    float m = vals[0];
    #pragma unroll
    for (int i = 1; i < 8; i++) m = fmaxf(m, vals[i]);
    #pragma unroll
    for (int off = 16; off > 0; off >>= 1)
        m = fmaxf(m, __shfl_xor_sync(0xFFFFFFFFu, m, off));
    if (lane == 0) red[warp] = m;
    __syncthreads();
    if (warp == 0) {
        float mm = red[lane & 7];
        #pragma unroll
        for (int off = 4; off > 0; off >>= 1)
            mm = fmaxf(mm, __shfl_xor_sync(0xFFFFFFFFu, mm, off));
        if (lane == 0) red[0] = mm;
    }
    __syncthreads();
    m = red[0];
    __syncthreads();

    // exp + sum
    float s = 0.0f;
    #pragma unroll
    for (int i = 0; i < 8; i++) {
        vals[i] = expf(vals[i] - m);
        s += vals[i];
    }
    #pragma unroll
    for (int off = 16; off > 0; off >>= 1)
        s += __shfl_xor_sync(0xFFFFFFFFu, s, off);
    if (lane == 0) red[warp] = s;
    __syncthreads();
    if (warp == 0) {
        float ss = red[lane & 7];
        #pragma unroll
        for (int off = 4; off > 0; off >>= 1)
            ss += __shfl_xor_sync(0xFFFFFFFFu, ss, off);
        if (lane == 0) red[0] = ss;
    }
    __syncthreads();
    const float inv = 1.0f / red[0];

    float4 o0 = make_float4(vals[0] * inv, vals[1] * inv, vals[2] * inv, vals[3] * inv);
    float4 o1 = make_float4(vals[4] * inv, vals[5] * inv, vals[6] * inv, vals[7] * inv);
    *reinterpret_cast<float4*>(&row[tid * 8])     = o0;
    *reinterpret_cast<float4*>(&row[tid * 8 + 4]) = o1;
}

// ---------------------------------------------------------------------------
// Kernel 4: ctx[b,s, h*64+d] = sum_j attn[bh][s][j] * V[bh][j][d]
// Per bh: C(2048 x 64) = A(2048 x 2048) @ B(2048 x 64). Block tile 64x64, BK=16.
// ---------------------------------------------------------------------------
__global__ __launch_bounds__(256) void ctx_kernel(
    const float* __restrict__ attn, const float* __restrict__ V,
    float* __restrict__ ctx)
{
    __shared__ float As[16][64];
    __shared__ float Bs[16][64];

    const int bh = blockIdx.y;
    const int b = bh >> 4;
    const int h = bh & 15;
    const float* Ah = attn + (size_t)bh * SS * SS;
    const float* Vh = V + (size_t)bh * SS * DK;

    const int tid = threadIdx.x;
    const int tx = tid & 15;
    const int ty = tid >> 4;
    const int iBase = blockIdx.x * 64;

    const int ar  = tid >> 2;
    const int ac4 = (tid & 3) * 4;
    const int bkr = tid >> 4;
    const int bc4 = (tid & 15) * 4;

    float acc[4][4];
    #pragma unroll
    for (int i = 0; i < 4; i++)
        #pragma unroll
        for (int j = 0; j < 4; j++) acc[i][j] = 0.0f;

    for (int k0 = 0; k0 < SS; k0 += 16) {
        float4 av = *reinterpret_cast<const float4*>(&Ah[(size_t)(iBase + ar) * SS + k0 + ac4]);
        As[ac4 + 0][ar] = av.x; As[ac4 + 1][ar] = av.y;
        As[ac4 + 2][ar] = av.z; As[ac4 + 3][ar] = av.w;
        float4 bv = *reinterpret_cast<const float4*>(&Vh[(size_t)(k0 + bkr) * DK + bc4]);
        *reinterpret_cast<float4*>(&Bs[bkr][bc4]) = bv;
        __syncthreads();

        #pragma unroll
        for (int k = 0; k < 16; k++) {
            float4 a = *reinterpret_cast<const float4*>(&As[k][ty * 4]);
            float4 bq = *reinterpret_cast<const float4*>(&Bs[k][tx * 4]);
            float ai[4] = {a.x, a.y, a.z, a.w};
            float bj[4] = {bq.x, bq.y, bq.z, bq.w};
            #pragma unroll
            for (int i = 0; i < 4; i++)
                #pragma unroll
                for (int j = 0; j < 4; j++)
                    acc[i][j] = fmaf(ai[i], bj[j], acc[i][j]);
        }
        __syncthreads();
    }

    #pragma unroll
    for (int i = 0; i < 4; i++) {
        const int s = iBase + ty * 4 + i;
        float* dst = ctx + ((size_t)(b * SS + s)) * DM + h * DK;
        #pragma unroll
        for (int j = 0; j < 4; j++) {
            dst[tx * 4 + j] = acc[i][j];
        }
    }
}

// ---------------------------------------------------------------------------
extern "C" void kernel_launch(void* const* d_in, const int* in_sizes, int n_in,
                              void* d_out, int out_size)
{
    const float* query = (const float*)d_in[0];
    const float* key   = (const float*)d_in[1];
    const float* value = (const float*)d_in[2];
    const float* Wq    = (const float*)d_in[3];
    const float* bq    = (const float*)d_in[4];
    const float* Wk    = (const float*)d_in[5];
    const float* bk    = (const float*)d_in[6];
    const float* Wv    = (const float*)d_in[7];
    const float* bv    = (const float*)d_in[8];
    const float* Wo    = (const float*)d_in[9];
    const float* bo    = (const float*)d_in[10];

    float* out_ptr  = (float*)d_out;                      // (B,S,D_MODEL)
    float* attn_ptr = (float*)d_out + (size_t)M_ROWS * DM; // (B,H,S,S)

    float* Qp;  cudaGetSymbolAddress((void**)&Qp,  g_Q);
    float* Kp;  cudaGetSymbolAddress((void**)&Kp,  g_K);
    float* Vp;  cudaGetSymbolAddress((void**)&Vp,  g_V);
    float* Cp;  cudaGetSymbolAddress((void**)&Cp,  g_ctx);

    dim3 gProj(DM / 64, M_ROWS / 64);   // (16, 64)
    proj_kernel<<<gProj, 256>>>(query, Wq, bq, Qp, 1);
    proj_kernel<<<gProj, 256>>>(key,   Wk, bk, Kp, 1);
    proj_kernel<<<gProj, 256>>>(value, Wv, bv, Vp, 1);

    dim3 gScores(SS / 64, SS / 64, BH); // (32, 32, 32)
    scores_kernel<<<gScores, 256>>>(Qp, Kp, attn_ptr);

    softmax_kernel<<<BH * SS, 256>>>(attn_ptr);           // 65536 rows

    dim3 gCtx(SS / 64, BH);             // (32, 32)
    ctx_kernel<<<gCtx, 256>>>(attn_ptr, Vp, Cp);

    proj_kernel<<<gProj, 256>>>(Cp, Wo, bo, out_ptr, 0);
}